// round 15
// baseline (speedup 1.0000x reference)
#include <cuda_runtime.h>
#include <cuda_bf16.h>
#include <cstdint>

#define BATCH 8192
#define MDIM  512
#define NDIM  2048

typedef __nv_bfloat16 bf16;

// ---------------- static device scratch (no allocs allowed) ----------------
__device__ __align__(256) bf16 g_xh[(size_t)BATCH * NDIM];
__device__ __align__(256) bf16 g_xl[(size_t)BATCH * NDIM];
__device__ __align__(256) bf16 g_rh[(size_t)BATCH * MDIM];
__device__ __align__(256) bf16 g_rl[(size_t)BATCH * MDIM];
__device__ __align__(256) bf16 g_yh[(size_t)BATCH * MDIM];
__device__ __align__(256) bf16 g_yl[(size_t)BATCH * MDIM];
__device__ __align__(256) bf16 g_Ah[(size_t)MDIM * NDIM];
__device__ __align__(256) bf16 g_Al[(size_t)MDIM * NDIM];
__device__ __align__(256) bf16 g_Wh[(size_t)NDIM * MDIM];
__device__ __align__(256) bf16 g_Wl[(size_t)NDIM * MDIM];
__device__ __align__(256) float g_part[2][(size_t)BATCH * MDIM];   // split-K partials
__device__ int g_cnt[256];   // per-tile tickets for fused combine (parity across launches)

// ---------------- PTX helpers (base-ISA only) ----------------
__device__ __forceinline__ uint32_t smem_u32(const void* p) {
    uint32_t a;
    asm("{ .reg .u64 t; cvta.to.shared.u64 t, %1; cvt.u32.u64 %0, t; }" : "=r"(a) : "l"(p));
    return a;
}
__device__ __forceinline__ void cpa16(uint32_t dst, const void* src) {
    asm volatile("cp.async.cg.shared.global [%0], [%1], 16;" :: "r"(dst), "l"(src));
}
__device__ __forceinline__ void cpa_commit() { asm volatile("cp.async.commit_group;" ::: "memory"); }
template<int N> __device__ __forceinline__ void cpa_wait() {
    asm volatile("cp.async.wait_group %0;" :: "n"(N) : "memory");
}
__device__ __forceinline__ void ldm_x4(uint32_t* r, uint32_t addr) {
    asm volatile("ldmatrix.sync.aligned.m8n8.x4.shared.b16 {%0,%1,%2,%3}, [%4];"
        : "=r"(r[0]), "=r"(r[1]), "=r"(r[2]), "=r"(r[3]) : "r"(addr));
}
__device__ __forceinline__ void mma_bf16(float* d, const uint32_t* a, const uint32_t* b) {
    asm volatile("mma.sync.aligned.m16n8k16.row.col.f32.bf16.bf16.f32 "
        "{%0,%1,%2,%3}, {%4,%5,%6,%7}, {%8,%9}, {%0,%1,%2,%3};"
        : "+f"(d[0]), "+f"(d[1]), "+f"(d[2]), "+f"(d[3])
        : "r"(a[0]), "r"(a[1]), "r"(a[2]), "r"(a[3]), "r"(b[0]), "r"(b[1]));
}

__device__ __forceinline__ void split2(float v0, float v1, bf16* h, bf16* l) {
    bf16 h0 = __float2bfloat16(v0), h1 = __float2bfloat16(v1);
    __nv_bfloat162 hp{h0, h1};
    __nv_bfloat162 lp{__float2bfloat16(v0 - __bfloat162float(h0)),
                      __float2bfloat16(v1 - __bfloat162float(h1))};
    *reinterpret_cast<__nv_bfloat162*>(h) = hp;
    *reinterpret_cast<__nv_bfloat162*>(l) = lp;
}

// ---------------- fp32 -> bf16 hi/lo split ----------------
__global__ void split_kernel(const float* __restrict__ s, bf16* __restrict__ h,
                             bf16* __restrict__ l, int n4) {
    int i = blockIdx.x * 256 + threadIdx.x;
    if (i >= n4) return;
    float4 v = reinterpret_cast<const float4*>(s)[i];
    split2(v.x, v.y, h + i * 4, l + i * 4);
    split2(v.z, v.w, h + i * 4 + 2, l + i * 4 + 2);
}

// ---------------- HMMA split-bf16 GEMM ----------------
// C[b,p] = sum_k X[b,k]*Wm[p,k]  (both K-major). 3-product split: hh + hl + lh.
// MODE 0: f = mu*acc               -> splits (outh/outl)
// MODE 2: f = (auxh+auxl) - mu*acc -> splits written IN PLACE over aux (outh/outl)
// MODE 3: split-K partial to outf[z]; LAST CTA of each tile fuses the combine:
//         r = own_acc + peer_partial - y -> splits (outh/outl)
#define PITCH 80
#define WT_B (128 * PITCH)

template<int MODE>
__global__ __launch_bounds__(256, 2)
void mma_gemm(const bf16* __restrict__ Xh, const bf16* __restrict__ Xl,
              const bf16* __restrict__ Bh, const bf16* __restrict__ Bl,
              int K, int P,
              float* __restrict__ outf, bf16* __restrict__ outh, bf16* __restrict__ outl,
              const bf16* __restrict__ auxh, const bf16* __restrict__ auxl,
              const float* __restrict__ yfull,
              const float* __restrict__ mu, int muidx)
{
    constexpr int XT_B  = 128 * PITCH;
    constexpr int STAGE = 2 * XT_B + 2 * WT_B;

    extern __shared__ char smem[];
    const uint32_t sb = smem_u32(smem);
    const int tid = threadIdx.x, lane = tid & 31, wid = tid >> 5;
    const int wr = wid >> 2, wc = wid & 3;
    const int b0 = blockIdx.x * 128, p0 = blockIdx.y * 128;
    const int koff = (MODE == 3) ? (int)blockIdx.z * (K >> 1) : 0;
    const int nch  = ((MODE == 3) ? (K >> 1) : K) >> 5;

    float acc[4][4][4];
    #pragma unroll
    for (int i = 0; i < 4; i++)
        #pragma unroll
        for (int j = 0; j < 4; j++)
            #pragma unroll
            for (int q = 0; q < 4; q++) acc[i][j][q] = 0.f;

    auto load_stage = [&](int s, int c) {
        const int k0 = koff + c * 32;
        const uint32_t st = sb + s * STAGE;
        const bf16* xs0 = Xh + (size_t)b0 * K + k0;
        const bf16* xs1 = Xl + (size_t)b0 * K + k0;
        const bf16* ws0 = Bh + (size_t)p0 * K + k0;
        const bf16* ws1 = Bl + (size_t)p0 * K + k0;
        #pragma unroll
        for (int l = 0; l < 8; l++) {
            int id = tid + l * 256;
            if (id < 1024) {
                int t = id >> 9, r = id & 511;
                int row = r >> 2, ch = r & 3;
                const bf16* g = t ? xs1 : xs0;
                cpa16(st + t * XT_B + row * PITCH + ch * 16,
                      g + (size_t)row * K + ch * 8);
            } else {
                int id2 = id - 1024;
                int t = id2 >> 9, r = id2 & 511;
                int row = r >> 2, ch = r & 3;
                const bf16* g = t ? ws1 : ws0;
                cpa16(st + 2 * XT_B + t * WT_B + row * PITCH + ch * 16,
                      g + (size_t)row * K + ch * 8);
            }
        }
        cpa_commit();
    };

    load_stage(0, 0);
    if (nch > 1) load_stage(1, 1);

    for (int c = 0; c < nch; c++) {
        const int s = c & 1;
        if (c + 1 < nch) cpa_wait<1>(); else cpa_wait<0>();
        __syncthreads();

        const uint32_t xs = sb + s * STAGE;
        const uint32_t ws = xs + 2 * XT_B;
        #pragma unroll
        for (int ks = 0; ks < 2; ks++) {
            const int kb = ks * 32;
            uint32_t ah[4][4], al[4][4];
            #pragma unroll
            for (int mi = 0; mi < 4; mi++) {
                uint32_t a = xs + (uint32_t)(wr * 64 + mi * 16 + (lane & 15)) * PITCH
                           + kb + ((lane >> 4) << 4);
                ldm_x4(ah[mi], a);
                ldm_x4(al[mi], a + XT_B);
            }
            #pragma unroll
            for (int nb = 0; nb < 2; nb++) {
                uint32_t a = ws + (uint32_t)(wc * 32 + nb * 16 + ((lane >> 4) << 3)
                           + (lane & 7)) * PITCH
                           + kb + (((lane >> 3) & 1) << 4);
                uint32_t bh[4], bl[4];
                ldm_x4(bh, a);
                ldm_x4(bl, a + WT_B);
                #pragma unroll
                for (int mi = 0; mi < 4; mi++) {
                    mma_bf16(acc[mi][nb*2],   ah[mi], bh);
                    mma_bf16(acc[mi][nb*2+1], ah[mi], bh + 2);
                }
                #pragma unroll
                for (int mi = 0; mi < 4; mi++) {
                    mma_bf16(acc[mi][nb*2],   ah[mi], bl);
                    mma_bf16(acc[mi][nb*2+1], ah[mi], bl + 2);
                }
                #pragma unroll
                for (int mi = 0; mi < 4; mi++) {
                    mma_bf16(acc[mi][nb*2],   al[mi], bh);
                    mma_bf16(acc[mi][nb*2+1], al[mi], bh + 2);
                }
            }
        }
        __syncthreads();
        if (c + 2 < nch) load_stage(s, c + 2);
    }

    // ---------------- epilogue ----------------
    const float m = (MODE == 0 || MODE == 2) ? mu[muidx] : 0.f;
    float* op = outf;
    if (MODE == 3) op = outf + (size_t)blockIdx.z * BATCH * MDIM;
    const int rbase = b0 + wr * 64 + (lane >> 2);
    const int cbase = p0 + wc * 32 + (lane & 3) * 2;

    #pragma unroll
    for (int mi = 0; mi < 4; mi++) {
        #pragma unroll
        for (int h = 0; h < 2; h++) {
            const int row = rbase + mi * 16 + h * 8;
            #pragma unroll
            for (int ni = 0; ni < 4; ni++) {
                const size_t off = (size_t)row * P + cbase + ni * 8;
                float v0 = acc[mi][ni][h * 2], v1 = acc[mi][ni][h * 2 + 1];
                if (MODE == 0) {
                    split2(m * v0, m * v1, outh + off, outl + off);
                } else if (MODE == 2) {
                    __nv_bfloat162 h2 = *reinterpret_cast<const __nv_bfloat162*>(auxh + off);
                    __nv_bfloat162 l2 = *reinterpret_cast<const __nv_bfloat162*>(auxl + off);
                    float a0 = __bfloat162float(h2.x) + __bfloat162float(l2.x);
                    float a1 = __bfloat162float(h2.y) + __bfloat162float(l2.y);
                    split2(a0 - m * v0, a1 - m * v1, outh + off, outl + off);
                } else {
                    *reinterpret_cast<float2*>(op + off) = make_float2(v0, v1);
                }
            }
        }
    }

    if (MODE == 3) {
        // fused split-K combine: last-arriving CTA of this tile emits r splits
        __shared__ int s_old;
        __threadfence();
        __syncthreads();
        if (tid == 0)
            s_old = atomicAdd(&g_cnt[blockIdx.x * 4 + blockIdx.y], 1);
        __syncthreads();
        if (s_old & 1) {   // exactly one of the 2 CTAs per tile per launch
            const float* peer = outf + (size_t)(blockIdx.z ^ 1) * BATCH * MDIM;
            #pragma unroll
            for (int mi = 0; mi < 4; mi++) {
                #pragma unroll
                for (int h = 0; h < 2; h++) {
                    const int row = rbase + mi * 16 + h * 8;
                    #pragma unroll
                    for (int ni = 0; ni < 4; ni++) {
                        const size_t off = (size_t)row * P + cbase + ni * 8;
                        float2 pp = *reinterpret_cast<const float2*>(peer + off);
                        float2 yy = *reinterpret_cast<const float2*>(yfull + off);
                        float r0 = acc[mi][ni][h * 2]     + pp.x - yy.x;
                        float r1 = acc[mi][ni][h * 2 + 1] + pp.y - yy.y;
                        split2(r0, r1, outh + off, outl + off);
                    }
                }
            }
        }
    }
}

// ---------------- shrink: reconstruct v = hi+lo, exact kth-largest, in-place ----------------
// LAST=0: write shrunk splits back to vh/vl.  LAST=1: write final fp32 x only.
template<int LAST>
__global__ __launch_bounds__(256, 4)
void shrink2(float* __restrict__ x, bf16* __restrict__ vh, bf16* __restrict__ vl,
             const float* __restrict__ beta, int bidx, int kth)
{
    __shared__ int wsum[2][8];
    const int tid = threadIdx.x, wid = tid >> 5, lane = tid & 31;
    const size_t go = (size_t)blockIdx.x * NDIM + tid * 8;

    uint4 hv = *reinterpret_cast<const uint4*>(vh + go);
    uint4 lv = *reinterpret_cast<const uint4*>(vl + go);
    float e[8];
    {
        const uint32_t* hp = &hv.x;
        const uint32_t* lp = &lv.x;
        #pragma unroll
        for (int q = 0; q < 4; q++) {
            __nv_bfloat162 h2 = *reinterpret_cast<const __nv_bfloat162*>(hp + q);
            __nv_bfloat162 l2 = *reinterpret_cast<const __nv_bfloat162*>(lp + q);
            e[q*2]   = __bfloat162float(h2.x) + __bfloat162float(l2.x);
            e[q*2+1] = __bfloat162float(h2.y) + __bfloat162float(l2.y);
        }
    }
    uint32_t k[8];
    #pragma unroll
    for (int i = 0; i < 8; i++) k[i] = __float_as_uint(fabsf(e[i]));

    uint32_t thr = 0;
    for (int bit = 30; bit >= 0; bit--) {
        uint32_t cand = thr | (1u << bit);
        int c = 0;
        #pragma unroll
        for (int i = 0; i < 8; i++) c += (k[i] >= cand);
        c = __reduce_add_sync(0xFFFFFFFFu, c);
        const int buf = bit & 1;
        if (lane == 0) wsum[buf][wid] = c;
        __syncthreads();
        int tot = wsum[buf][0]+wsum[buf][1]+wsum[buf][2]+wsum[buf][3]
                + wsum[buf][4]+wsum[buf][5]+wsum[buf][6]+wsum[buf][7];
        if (tot >= kth) thr = cand;
    }

    const float thf = __uint_as_float(thr);
    const float b = beta[bidx];
    float r[8];
    #pragma unroll
    for (int i = 0; i < 8; i++) {
        float val = e[i];
        float u = val / b;
        float soft = b * copysignf(fmaxf(fabsf(u) - 1.0f, 0.0f), u);
        r[i] = (fabsf(val) >= thf) ? val : soft;
    }

    if (LAST) {
        float* row = x + go;
        *reinterpret_cast<float4*>(row)     = make_float4(r[0], r[1], r[2], r[3]);
        *reinterpret_cast<float4*>(row + 4) = make_float4(r[4], r[5], r[6], r[7]);
    } else {
        #pragma unroll
        for (int i = 0; i < 8; i += 2)
            split2(r[i], r[i+1], vh + go + i, vl + go + i);
    }
}

// ---------------------------------------------------------------------------
extern "C" void kernel_launch(void* const* d_in, const int* in_sizes, int n_in,
                              void* d_out, int out_size)
{
    const float* y    = (const float*)d_in[0];   // [8192, 512]
    const float* A    = (const float*)d_in[1];   // [512, 2048]
    const float* W    = (const float*)d_in[2];   // [2048, 512] = A^T
    const float* beta = (const float*)d_in[3];
    const float* mu   = (const float*)d_in[4];
    float* x = (float*)d_out;                    // [8192, 2048]

    constexpr int SMEM_128 = 2 * (2 * 128 * PITCH + 2 * WT_B);   // 81920

    cudaFuncSetAttribute(mma_gemm<0>, cudaFuncAttributeMaxDynamicSharedMemorySize, SMEM_128);
    cudaFuncSetAttribute(mma_gemm<2>, cudaFuncAttributeMaxDynamicSharedMemorySize, SMEM_128);
    cudaFuncSetAttribute(mma_gemm<3>, cudaFuncAttributeMaxDynamicSharedMemorySize, SMEM_128);

    bf16 *xh, *xl, *rh, *rl, *yh, *yl, *Ahp, *Alp, *Wh, *Wl;
    float *part;
    { void* p; cudaGetSymbolAddress(&p, g_xh); xh = (bf16*)p; }
    { void* p; cudaGetSymbolAddress(&p, g_xl); xl = (bf16*)p; }
    { void* p; cudaGetSymbolAddress(&p, g_rh); rh = (bf16*)p; }
    { void* p; cudaGetSymbolAddress(&p, g_rl); rl = (bf16*)p; }
    { void* p; cudaGetSymbolAddress(&p, g_yh); yh = (bf16*)p; }
    { void* p; cudaGetSymbolAddress(&p, g_yl); yl = (bf16*)p; }
    { void* p; cudaGetSymbolAddress(&p, g_Ah); Ahp = (bf16*)p; }
    { void* p; cudaGetSymbolAddress(&p, g_Al); Alp = (bf16*)p; }
    { void* p; cudaGetSymbolAddress(&p, g_Wh); Wh = (bf16*)p; }
    { void* p; cudaGetSymbolAddress(&p, g_Wl); Wl = (bf16*)p; }
    { void* p; cudaGetSymbolAddress(&p, g_part); part = (float*)p; }

    // splits of inputs
    {
        int n4 = BATCH * MDIM / 4;
        split_kernel<<<(n4 + 255) / 256, 256>>>(y, yh, yl, n4);
        n4 = MDIM * NDIM / 4;
        split_kernel<<<(n4 + 255) / 256, 256>>>(A, Ahp, Alp, n4);
        split_kernel<<<(n4 + 255) / 256, 256>>>(W, Wh, Wl, n4);
    }

    const dim3 blk(256);
    const dim3 gN(BATCH / 128, NDIM / 128);       // (64, 16)  1024 CTAs
    const dim3 gM(BATCH / 128, MDIM / 128, 2);    // (64, 4, 2) 512 CTAs split-K
    const int kth[6] = {0, 24, 49, 73, 98, 122};

    // x0 = mu0 * (y @ A): splits only
    mma_gemm<0><<<gN, blk, SMEM_128>>>(yh, yl, Wh, Wl, MDIM, NDIM,
                                       nullptr, xh, xl, nullptr, nullptr, nullptr, mu, 0);

    for (int t = 1; t <= 5; t++) {
        // split-K partials of x @ A.T + fused combine -> rh/rl
        mma_gemm<3><<<gM, blk, SMEM_128>>>(xh, xl, Ahp, Alp, NDIM, MDIM,
                                           part, rh, rl, nullptr, nullptr, y, mu, t);
        // v = (xh+xl) - mu*(r @ W.T) -> splits written in place over xh/xl
        mma_gemm<2><<<gN, blk, SMEM_128>>>(rh, rl, Wh, Wl, MDIM, NDIM,
                                           nullptr, xh, xl, xh, xl, nullptr, mu, t);
        // x = shrink(v): t<5 -> splits in place; t=5 -> final fp32 output
        if (t < 5)
            shrink2<0><<<BATCH, blk>>>(x, xh, xl, beta, t, kth[t]);
        else
            shrink2<1><<<BATCH, blk>>>(x, xh, xl, beta, t, kth[t]);
    }
}

// round 16
// speedup vs baseline: 1.0202x; 1.0202x over previous
#include <cuda_runtime.h>
#include <cuda_bf16.h>
#include <cstdint>

#define BATCH 8192
#define MDIM  512
#define NDIM  2048

typedef __nv_bfloat16 bf16;

// ---------------- static device scratch (no allocs allowed) ----------------
__device__ __align__(256) bf16 g_xh[(size_t)BATCH * NDIM];
__device__ __align__(256) bf16 g_xl[(size_t)BATCH * NDIM];
__device__ __align__(256) bf16 g_rh[(size_t)BATCH * MDIM];
__device__ __align__(256) bf16 g_rl[(size_t)BATCH * MDIM];
__device__ __align__(256) bf16 g_yh[(size_t)BATCH * MDIM];
__device__ __align__(256) bf16 g_yl[(size_t)BATCH * MDIM];
__device__ __align__(256) bf16 g_Ah[(size_t)MDIM * NDIM];
__device__ __align__(256) bf16 g_Al[(size_t)MDIM * NDIM];
__device__ __align__(256) bf16 g_Wh[(size_t)NDIM * MDIM];
__device__ __align__(256) bf16 g_Wl[(size_t)NDIM * MDIM];
__device__ __align__(256) float g_part[2][(size_t)BATCH * MDIM];   // split-K partials

// ---------------- PTX helpers (base-ISA only) ----------------
__device__ __forceinline__ uint32_t smem_u32(const void* p) {
    uint32_t a;
    asm("{ .reg .u64 t; cvta.to.shared.u64 t, %1; cvt.u32.u64 %0, t; }" : "=r"(a) : "l"(p));
    return a;
}
__device__ __forceinline__ void cpa16(uint32_t dst, const void* src) {
    asm volatile("cp.async.cg.shared.global [%0], [%1], 16;" :: "r"(dst), "l"(src));
}
__device__ __forceinline__ void cpa_commit() { asm volatile("cp.async.commit_group;" ::: "memory"); }
template<int N> __device__ __forceinline__ void cpa_wait() {
    asm volatile("cp.async.wait_group %0;" :: "n"(N) : "memory");
}
__device__ __forceinline__ void ldm_x4(uint32_t* r, uint32_t addr) {
    asm volatile("ldmatrix.sync.aligned.m8n8.x4.shared.b16 {%0,%1,%2,%3}, [%4];"
        : "=r"(r[0]), "=r"(r[1]), "=r"(r[2]), "=r"(r[3]) : "r"(addr));
}
__device__ __forceinline__ void mma_bf16(float* d, const uint32_t* a, const uint32_t* b) {
    asm volatile("mma.sync.aligned.m16n8k16.row.col.f32.bf16.bf16.f32 "
        "{%0,%1,%2,%3}, {%4,%5,%6,%7}, {%8,%9}, {%0,%1,%2,%3};"
        : "+f"(d[0]), "+f"(d[1]), "+f"(d[2]), "+f"(d[3])
        : "r"(a[0]), "r"(a[1]), "r"(a[2]), "r"(a[3]), "r"(b[0]), "r"(b[1]));
}

__device__ __forceinline__ void split2(float v0, float v1, bf16* h, bf16* l) {
    bf16 h0 = __float2bfloat16(v0), h1 = __float2bfloat16(v1);
    __nv_bfloat162 hp{h0, h1};
    __nv_bfloat162 lp{__float2bfloat16(v0 - __bfloat162float(h0)),
                      __float2bfloat16(v1 - __bfloat162float(h1))};
    *reinterpret_cast<__nv_bfloat162*>(h) = hp;
    *reinterpret_cast<__nv_bfloat162*>(l) = lp;
}

// ---------------- fp32 -> bf16 hi/lo split ----------------
__global__ void split_kernel(const float* __restrict__ s, bf16* __restrict__ h,
                             bf16* __restrict__ l, int n4) {
    int i = blockIdx.x * 256 + threadIdx.x;
    if (i >= n4) return;
    float4 v = reinterpret_cast<const float4*>(s)[i];
    split2(v.x, v.y, h + i * 4, l + i * 4);
    split2(v.z, v.w, h + i * 4 + 2, l + i * 4 + 2);
}

// ---------------- combine split-K partials: r = p0 + p1 - y -> splits ----------------
__global__ void combine_r(const float* __restrict__ p0, const float* __restrict__ p1,
                          const float* __restrict__ y, bf16* __restrict__ rh,
                          bf16* __restrict__ rl, int n4) {
    int i = blockIdx.x * 256 + threadIdx.x;
    if (i >= n4) return;
    float4 a = reinterpret_cast<const float4*>(p0)[i];
    float4 b = reinterpret_cast<const float4*>(p1)[i];
    float4 c = reinterpret_cast<const float4*>(y)[i];
    split2(a.x + b.x - c.x, a.y + b.y - c.y, rh + i * 4, rl + i * 4);
    split2(a.z + b.z - c.z, a.w + b.w - c.w, rh + i * 4 + 2, rl + i * 4 + 2);
}

// ---------------- HMMA split-bf16 GEMM ----------------
// C[b,p] = sum_k X[b,k]*Wm[p,k]  (both K-major). 3-product split: hh + hl + lh.
// MODE 0: f = mu*acc               -> splits (outh/outl)
// MODE 2: f = (auxh+auxl) - mu*acc -> splits written IN PLACE over aux (outh/outl)
// MODE 3: split-K partial, f = acc -> outf[blockIdx.z * BATCH*MDIM + ...]
#define PITCH 80
#define WT_B (128 * PITCH)

template<int MODE>
__global__ __launch_bounds__(256, 2)
void mma_gemm(const bf16* __restrict__ Xh, const bf16* __restrict__ Xl,
              const bf16* __restrict__ Bh, const bf16* __restrict__ Bl,
              int K, int P,
              float* __restrict__ outf, bf16* __restrict__ outh, bf16* __restrict__ outl,
              const bf16* __restrict__ auxh, const bf16* __restrict__ auxl,
              const float* __restrict__ mu, int muidx)
{
    constexpr int XT_B  = 128 * PITCH;
    constexpr int STAGE = 2 * XT_B + 2 * WT_B;

    extern __shared__ char smem[];
    const uint32_t sb = smem_u32(smem);
    const int tid = threadIdx.x, lane = tid & 31, wid = tid >> 5;
    const int wr = wid >> 2, wc = wid & 3;
    const int b0 = blockIdx.x * 128, p0 = blockIdx.y * 128;
    const int koff = (MODE == 3) ? (int)blockIdx.z * (K >> 1) : 0;
    const int nch  = ((MODE == 3) ? (K >> 1) : K) >> 5;

    float acc[4][4][4];
    #pragma unroll
    for (int i = 0; i < 4; i++)
        #pragma unroll
        for (int j = 0; j < 4; j++)
            #pragma unroll
            for (int q = 0; q < 4; q++) acc[i][j][q] = 0.f;

    auto load_stage = [&](int s, int c) {
        const int k0 = koff + c * 32;
        const uint32_t st = sb + s * STAGE;
        const bf16* xs0 = Xh + (size_t)b0 * K + k0;
        const bf16* xs1 = Xl + (size_t)b0 * K + k0;
        const bf16* ws0 = Bh + (size_t)p0 * K + k0;
        const bf16* ws1 = Bl + (size_t)p0 * K + k0;
        #pragma unroll
        for (int l = 0; l < 8; l++) {
            int id = tid + l * 256;
            if (id < 1024) {
                int t = id >> 9, r = id & 511;
                int row = r >> 2, ch = r & 3;
                const bf16* g = t ? xs1 : xs0;
                cpa16(st + t * XT_B + row * PITCH + ch * 16,
                      g + (size_t)row * K + ch * 8);
            } else {
                int id2 = id - 1024;
                int t = id2 >> 9, r = id2 & 511;
                int row = r >> 2, ch = r & 3;
                const bf16* g = t ? ws1 : ws0;
                cpa16(st + 2 * XT_B + t * WT_B + row * PITCH + ch * 16,
                      g + (size_t)row * K + ch * 8);
            }
        }
        cpa_commit();
    };

    load_stage(0, 0);
    if (nch > 1) load_stage(1, 1);

    for (int c = 0; c < nch; c++) {
        const int s = c & 1;
        if (c + 1 < nch) cpa_wait<1>(); else cpa_wait<0>();
        __syncthreads();

        const uint32_t xs = sb + s * STAGE;
        const uint32_t ws = xs + 2 * XT_B;
        #pragma unroll
        for (int ks = 0; ks < 2; ks++) {
            const int kb = ks * 32;
            uint32_t ah[4][4], al[4][4];
            #pragma unroll
            for (int mi = 0; mi < 4; mi++) {
                uint32_t a = xs + (uint32_t)(wr * 64 + mi * 16 + (lane & 15)) * PITCH
                           + kb + ((lane >> 4) << 4);
                ldm_x4(ah[mi], a);
                ldm_x4(al[mi], a + XT_B);
            }
            #pragma unroll
            for (int nb = 0; nb < 2; nb++) {
                uint32_t a = ws + (uint32_t)(wc * 32 + nb * 16 + ((lane >> 4) << 3)
                           + (lane & 7)) * PITCH
                           + kb + (((lane >> 3) & 1) << 4);
                uint32_t bh[4], bl[4];
                ldm_x4(bh, a);
                ldm_x4(bl, a + WT_B);
                #pragma unroll
                for (int mi = 0; mi < 4; mi++) {
                    mma_bf16(acc[mi][nb*2],   ah[mi], bh);
                    mma_bf16(acc[mi][nb*2+1], ah[mi], bh + 2);
                }
                #pragma unroll
                for (int mi = 0; mi < 4; mi++) {
                    mma_bf16(acc[mi][nb*2],   ah[mi], bl);
                    mma_bf16(acc[mi][nb*2+1], ah[mi], bl + 2);
                }
                #pragma unroll
                for (int mi = 0; mi < 4; mi++) {
                    mma_bf16(acc[mi][nb*2],   al[mi], bh);
                    mma_bf16(acc[mi][nb*2+1], al[mi], bh + 2);
                }
            }
        }
        __syncthreads();
        if (c + 2 < nch) load_stage(s, c + 2);
    }

    // ---------------- epilogue ----------------
    const float m = (MODE == 0 || MODE == 2) ? mu[muidx] : 0.f;
    float* op = outf;
    if (MODE == 3) op = outf + (size_t)blockIdx.z * BATCH * MDIM;
    const int rbase = b0 + wr * 64 + (lane >> 2);
    const int cbase = p0 + wc * 32 + (lane & 3) * 2;

    #pragma unroll
    for (int mi = 0; mi < 4; mi++) {
        #pragma unroll
        for (int h = 0; h < 2; h++) {
            const int row = rbase + mi * 16 + h * 8;
            #pragma unroll
            for (int ni = 0; ni < 4; ni++) {
                const size_t off = (size_t)row * P + cbase + ni * 8;
                float v0 = acc[mi][ni][h * 2], v1 = acc[mi][ni][h * 2 + 1];
                if (MODE == 0) {
                    split2(m * v0, m * v1, outh + off, outl + off);
                } else if (MODE == 2) {
                    __nv_bfloat162 h2 = *reinterpret_cast<const __nv_bfloat162*>(auxh + off);
                    __nv_bfloat162 l2 = *reinterpret_cast<const __nv_bfloat162*>(auxl + off);
                    float a0 = __bfloat162float(h2.x) + __bfloat162float(l2.x);
                    float a1 = __bfloat162float(h2.y) + __bfloat162float(l2.y);
                    split2(a0 - m * v0, a1 - m * v1, outh + off, outl + off);
                } else {
                    *reinterpret_cast<float2*>(op + off) = make_float2(v0, v1);
                }
            }
        }
    }
}

// ---------------- shrink: reconstruct v = hi+lo, exact kth-largest, in-place ----------------
// LAST=0: write shrunk splits back to vh/vl.  LAST=1: write final fp32 x only.
template<int LAST>
__global__ __launch_bounds__(256, 4)
void shrink2(float* __restrict__ x, bf16* __restrict__ vh, bf16* __restrict__ vl,
             const float* __restrict__ beta, int bidx, int kth)
{
    __shared__ int wsum[2][8];
    const int tid = threadIdx.x, wid = tid >> 5, lane = tid & 31;
    const size_t go = (size_t)blockIdx.x * NDIM + tid * 8;

    uint4 hv = *reinterpret_cast<const uint4*>(vh + go);
    uint4 lv = *reinterpret_cast<const uint4*>(vl + go);
    float e[8];
    {
        const uint32_t* hp = &hv.x;
        const uint32_t* lp = &lv.x;
        #pragma unroll
        for (int q = 0; q < 4; q++) {
            __nv_bfloat162 h2 = *reinterpret_cast<const __nv_bfloat162*>(hp + q);
            __nv_bfloat162 l2 = *reinterpret_cast<const __nv_bfloat162*>(lp + q);
            e[q*2]   = __bfloat162float(h2.x) + __bfloat162float(l2.x);
            e[q*2+1] = __bfloat162float(h2.y) + __bfloat162float(l2.y);
        }
    }
    uint32_t k[8];
    #pragma unroll
    for (int i = 0; i < 8; i++) k[i] = __float_as_uint(fabsf(e[i]));

    uint32_t thr = 0;
    for (int bit = 30; bit >= 0; bit--) {
        uint32_t cand = thr | (1u << bit);
        int c = 0;
        #pragma unroll
        for (int i = 0; i < 8; i++) c += (k[i] >= cand);
        c = __reduce_add_sync(0xFFFFFFFFu, c);
        const int buf = bit & 1;
        if (lane == 0) wsum[buf][wid] = c;
        __syncthreads();
        int tot = wsum[buf][0]+wsum[buf][1]+wsum[buf][2]+wsum[buf][3]
                + wsum[buf][4]+wsum[buf][5]+wsum[buf][6]+wsum[buf][7];
        if (tot >= kth) thr = cand;
    }

    const float thf = __uint_as_float(thr);
    const float b = beta[bidx];
    float r[8];
    #pragma unroll
    for (int i = 0; i < 8; i++) {
        float val = e[i];
        float u = val / b;
        float soft = b * copysignf(fmaxf(fabsf(u) - 1.0f, 0.0f), u);
        r[i] = (fabsf(val) >= thf) ? val : soft;
    }

    if (LAST) {
        float* row = x + go;
        *reinterpret_cast<float4*>(row)     = make_float4(r[0], r[1], r[2], r[3]);
        *reinterpret_cast<float4*>(row + 4) = make_float4(r[4], r[5], r[6], r[7]);
    } else {
        #pragma unroll
        for (int i = 0; i < 8; i += 2)
            split2(r[i], r[i+1], vh + go + i, vl + go + i);
    }
}

// ---------------------------------------------------------------------------
extern "C" void kernel_launch(void* const* d_in, const int* in_sizes, int n_in,
                              void* d_out, int out_size)
{
    const float* y    = (const float*)d_in[0];   // [8192, 512]
    const float* A    = (const float*)d_in[1];   // [512, 2048]
    const float* W    = (const float*)d_in[2];   // [2048, 512] = A^T
    const float* beta = (const float*)d_in[3];
    const float* mu   = (const float*)d_in[4];
    float* x = (float*)d_out;                    // [8192, 2048]

    constexpr int SMEM_128 = 2 * (2 * 128 * PITCH + 2 * WT_B);   // 81920

    cudaFuncSetAttribute(mma_gemm<0>, cudaFuncAttributeMaxDynamicSharedMemorySize, SMEM_128);
    cudaFuncSetAttribute(mma_gemm<2>, cudaFuncAttributeMaxDynamicSharedMemorySize, SMEM_128);
    cudaFuncSetAttribute(mma_gemm<3>, cudaFuncAttributeMaxDynamicSharedMemorySize, SMEM_128);

    bf16 *xh, *xl, *rh, *rl, *yh, *yl, *Ahp, *Alp, *Wh, *Wl;
    float *part;
    { void* p; cudaGetSymbolAddress(&p, g_xh); xh = (bf16*)p; }
    { void* p; cudaGetSymbolAddress(&p, g_xl); xl = (bf16*)p; }
    { void* p; cudaGetSymbolAddress(&p, g_rh); rh = (bf16*)p; }
    { void* p; cudaGetSymbolAddress(&p, g_rl); rl = (bf16*)p; }
    { void* p; cudaGetSymbolAddress(&p, g_yh); yh = (bf16*)p; }
    { void* p; cudaGetSymbolAddress(&p, g_yl); yl = (bf16*)p; }
    { void* p; cudaGetSymbolAddress(&p, g_Ah); Ahp = (bf16*)p; }
    { void* p; cudaGetSymbolAddress(&p, g_Al); Alp = (bf16*)p; }
    { void* p; cudaGetSymbolAddress(&p, g_Wh); Wh = (bf16*)p; }
    { void* p; cudaGetSymbolAddress(&p, g_Wl); Wl = (bf16*)p; }
    { void* p; cudaGetSymbolAddress(&p, g_part); part = (float*)p; }

    // splits of inputs
    {
        int n4 = BATCH * MDIM / 4;
        split_kernel<<<(n4 + 255) / 256, 256>>>(y, yh, yl, n4);
        n4 = MDIM * NDIM / 4;
        split_kernel<<<(n4 + 255) / 256, 256>>>(A, Ahp, Alp, n4);
        split_kernel<<<(n4 + 255) / 256, 256>>>(W, Wh, Wl, n4);
    }

    const dim3 blk(256);
    const dim3 gN(BATCH / 128, NDIM / 128);       // (64, 16)  1024 CTAs
    const dim3 gM(BATCH / 128, MDIM / 128, 2);    // (64, 4, 2) 512 CTAs split-K
    const int kth[6] = {0, 24, 49, 73, 98, 122};
    const int nr4 = BATCH * MDIM / 4;

    // x0 = mu0 * (y @ A): splits only
    mma_gemm<0><<<gN, blk, SMEM_128>>>(yh, yl, Wh, Wl, MDIM, NDIM,
                                       nullptr, xh, xl, nullptr, nullptr, mu, 0);

    for (int t = 1; t <= 5; t++) {
        // split-K partials of x @ A.T
        mma_gemm<3><<<gM, blk, SMEM_128>>>(xh, xl, Ahp, Alp, NDIM, MDIM,
                                           part, nullptr, nullptr, nullptr, nullptr, mu, t);
        // r = p0 + p1 - y  -> rh/rl splits
        combine_r<<<(nr4 + 255) / 256, blk>>>(part, part + (size_t)BATCH * MDIM, y,
                                              rh, rl, nr4);
        // v = (xh+xl) - mu*(r @ W.T) -> splits written in place over xh/xl
        mma_gemm<2><<<gN, blk, SMEM_128>>>(rh, rl, Wh, Wl, MDIM, NDIM,
                                           nullptr, xh, xl, xh, xl, mu, t);
        // x = shrink(v): t<5 -> splits in place; t=5 -> final fp32 output
        if (t < 5)
            shrink2<0><<<BATCH, blk>>>(x, xh, xl, beta, t, kth[t]);
        else
            shrink2<1><<<BATCH, blk>>>(x, xh, xl, beta, t, kth[t]);
    }
}

// round 17
// speedup vs baseline: 1.0415x; 1.0208x over previous
#include <cuda_runtime.h>
#include <cuda_bf16.h>
#include <cstdint>

#define BATCH 8192
#define MDIM  512
#define NDIM  2048

typedef __nv_bfloat16 bf16;

// ---------------- static device scratch (no allocs allowed) ----------------
__device__ __align__(256) bf16 g_xh[(size_t)BATCH * NDIM];
__device__ __align__(256) bf16 g_xl[(size_t)BATCH * NDIM];
__device__ __align__(256) bf16 g_rh[(size_t)BATCH * MDIM];
__device__ __align__(256) bf16 g_rl[(size_t)BATCH * MDIM];
__device__ __align__(256) bf16 g_yh[(size_t)BATCH * MDIM];
__device__ __align__(256) bf16 g_yl[(size_t)BATCH * MDIM];
__device__ __align__(256) bf16 g_Ah[(size_t)MDIM * NDIM];
__device__ __align__(256) bf16 g_Al[(size_t)MDIM * NDIM];
__device__ __align__(256) bf16 g_Wh[(size_t)NDIM * MDIM];
__device__ __align__(256) bf16 g_Wl[(size_t)NDIM * MDIM];
__device__ __align__(256) float g_part[2][(size_t)BATCH * MDIM];   // split-K partials

// ---------------- PTX helpers (base-ISA only) ----------------
__device__ __forceinline__ uint32_t smem_u32(const void* p) {
    uint32_t a;
    asm("{ .reg .u64 t; cvta.to.shared.u64 t, %1; cvt.u32.u64 %0, t; }" : "=r"(a) : "l"(p));
    return a;
}
__device__ __forceinline__ void cpa16(uint32_t dst, const void* src) {
    asm volatile("cp.async.cg.shared.global [%0], [%1], 16;" :: "r"(dst), "l"(src));
}
__device__ __forceinline__ void cpa_commit() { asm volatile("cp.async.commit_group;" ::: "memory"); }
template<int N> __device__ __forceinline__ void cpa_wait() {
    asm volatile("cp.async.wait_group %0;" :: "n"(N) : "memory");
}
__device__ __forceinline__ void ldm_x4(uint32_t* r, uint32_t addr) {
    asm volatile("ldmatrix.sync.aligned.m8n8.x4.shared.b16 {%0,%1,%2,%3}, [%4];"
        : "=r"(r[0]), "=r"(r[1]), "=r"(r[2]), "=r"(r[3]) : "r"(addr));
}
__device__ __forceinline__ void mma_bf16(float* d, const uint32_t* a, const uint32_t* b) {
    asm volatile("mma.sync.aligned.m16n8k16.row.col.f32.bf16.bf16.f32 "
        "{%0,%1,%2,%3}, {%4,%5,%6,%7}, {%8,%9}, {%0,%1,%2,%3};"
        : "+f"(d[0]), "+f"(d[1]), "+f"(d[2]), "+f"(d[3])
        : "r"(a[0]), "r"(a[1]), "r"(a[2]), "r"(a[3]), "r"(b[0]), "r"(b[1]));
}

__device__ __forceinline__ void split2(float v0, float v1, bf16* h, bf16* l) {
    bf16 h0 = __float2bfloat16(v0), h1 = __float2bfloat16(v1);
    __nv_bfloat162 hp{h0, h1};
    __nv_bfloat162 lp{__float2bfloat16(v0 - __bfloat162float(h0)),
                      __float2bfloat16(v1 - __bfloat162float(h1))};
    *reinterpret_cast<__nv_bfloat162*>(h) = hp;
    *reinterpret_cast<__nv_bfloat162*>(l) = lp;
}

// ---------------- fused fp32 -> bf16 hi/lo split of y, A, W ----------------
#define NY4 (BATCH * MDIM / 4)
#define NA4 (MDIM * NDIM / 4)

__global__ void split3_kernel(const float* __restrict__ y, bf16* __restrict__ yh, bf16* __restrict__ yl,
                              const float* __restrict__ A, bf16* __restrict__ Ah, bf16* __restrict__ Al,
                              const float* __restrict__ W, bf16* __restrict__ Wh, bf16* __restrict__ Wl)
{
    int i = blockIdx.x * 256 + threadIdx.x;
    const float* s; bf16 *h, *l; int j;
    if (i < NY4)                { s = y; h = yh; l = yl; j = i; }
    else if (i < NY4 + NA4)     { s = A; h = Ah; l = Al; j = i - NY4; }
    else if (i < NY4 + 2 * NA4) { s = W; h = Wh; l = Wl; j = i - NY4 - NA4; }
    else return;
    float4 v = reinterpret_cast<const float4*>(s)[j];
    split2(v.x, v.y, h + j * 4, l + j * 4);
    split2(v.z, v.w, h + j * 4 + 2, l + j * 4 + 2);
}

// ---------------- combine split-K partials: r = p0 + p1 - y -> splits ----------------
__global__ void combine_r(const float* __restrict__ p0, const float* __restrict__ p1,
                          const float* __restrict__ y, bf16* __restrict__ rh,
                          bf16* __restrict__ rl, int n4) {
    int i = blockIdx.x * 256 + threadIdx.x;
    if (i >= n4) return;
    float4 a = reinterpret_cast<const float4*>(p0)[i];
    float4 b = reinterpret_cast<const float4*>(p1)[i];
    float4 c = reinterpret_cast<const float4*>(y)[i];
    split2(a.x + b.x - c.x, a.y + b.y - c.y, rh + i * 4, rl + i * 4);
    split2(a.z + b.z - c.z, a.w + b.w - c.w, rh + i * 4 + 2, rl + i * 4 + 2);
}

// ---------------- HMMA split-bf16 GEMM ----------------
// C[b,p] = sum_k X[b,k]*Wm[p,k]  (both K-major). 3-product split: hh + hl + lh.
// MODE 0: f = mu*acc                   -> splits only (outh/outl)
// MODE 2: f = (auxh+auxl) - mu*acc     -> outf fp32
// MODE 3: split-K partial, f = acc     -> outf[blockIdx.z * BATCH*MDIM + ...]
#define PITCH 80
#define WT_B (128 * PITCH)

template<int MODE>
__global__ __launch_bounds__(256, 2)
void mma_gemm(const bf16* __restrict__ Xh, const bf16* __restrict__ Xl,
              const bf16* __restrict__ Bh, const bf16* __restrict__ Bl,
              int K, int P,
              float* __restrict__ outf, bf16* __restrict__ outh, bf16* __restrict__ outl,
              const bf16* __restrict__ auxh, const bf16* __restrict__ auxl,
              const float* __restrict__ mu, int muidx)
{
    constexpr int XT_B  = 128 * PITCH;
    constexpr int STAGE = 2 * XT_B + 2 * WT_B;

    extern __shared__ char smem[];
    const uint32_t sb = smem_u32(smem);
    const int tid = threadIdx.x, lane = tid & 31, wid = tid >> 5;
    const int wr = wid >> 2, wc = wid & 3;
    const int b0 = blockIdx.x * 128, p0 = blockIdx.y * 128;
    const int koff = (MODE == 3) ? (int)blockIdx.z * (K >> 1) : 0;
    const int nch  = ((MODE == 3) ? (K >> 1) : K) >> 5;

    float acc[4][4][4];
    #pragma unroll
    for (int i = 0; i < 4; i++)
        #pragma unroll
        for (int j = 0; j < 4; j++)
            #pragma unroll
            for (int q = 0; q < 4; q++) acc[i][j][q] = 0.f;

    auto load_stage = [&](int s, int c) {
        const int k0 = koff + c * 32;
        const uint32_t st = sb + s * STAGE;
        const bf16* xs0 = Xh + (size_t)b0 * K + k0;
        const bf16* xs1 = Xl + (size_t)b0 * K + k0;
        const bf16* ws0 = Bh + (size_t)p0 * K + k0;
        const bf16* ws1 = Bl + (size_t)p0 * K + k0;
        #pragma unroll
        for (int l = 0; l < 8; l++) {
            int id = tid + l * 256;
            if (id < 1024) {
                int t = id >> 9, r = id & 511;
                int row = r >> 2, ch = r & 3;
                const bf16* g = t ? xs1 : xs0;
                cpa16(st + t * XT_B + row * PITCH + ch * 16,
                      g + (size_t)row * K + ch * 8);
            } else {
                int id2 = id - 1024;
                int t = id2 >> 9, r = id2 & 511;
                int row = r >> 2, ch = r & 3;
                const bf16* g = t ? ws1 : ws0;
                cpa16(st + 2 * XT_B + t * WT_B + row * PITCH + ch * 16,
                      g + (size_t)row * K + ch * 8);
            }
        }
        cpa_commit();
    };

    load_stage(0, 0);
    if (nch > 1) load_stage(1, 1);

    for (int c = 0; c < nch; c++) {
        const int s = c & 1;
        if (c + 1 < nch) cpa_wait<1>(); else cpa_wait<0>();
        __syncthreads();

        const uint32_t xs = sb + s * STAGE;
        const uint32_t ws = xs + 2 * XT_B;
        #pragma unroll
        for (int ks = 0; ks < 2; ks++) {
            const int kb = ks * 32;
            uint32_t ah[4][4], al[4][4];
            #pragma unroll
            for (int mi = 0; mi < 4; mi++) {
                uint32_t a = xs + (uint32_t)(wr * 64 + mi * 16 + (lane & 15)) * PITCH
                           + kb + ((lane >> 4) << 4);
                ldm_x4(ah[mi], a);
                ldm_x4(al[mi], a + XT_B);
            }
            #pragma unroll
            for (int nb = 0; nb < 2; nb++) {
                uint32_t a = ws + (uint32_t)(wc * 32 + nb * 16 + ((lane >> 4) << 3)
                           + (lane & 7)) * PITCH
                           + kb + (((lane >> 3) & 1) << 4);
                uint32_t bh[4], bl[4];
                ldm_x4(bh, a);
                ldm_x4(bl, a + WT_B);
                #pragma unroll
                for (int mi = 0; mi < 4; mi++) {
                    mma_bf16(acc[mi][nb*2],   ah[mi], bh);
                    mma_bf16(acc[mi][nb*2+1], ah[mi], bh + 2);
                }
                #pragma unroll
                for (int mi = 0; mi < 4; mi++) {
                    mma_bf16(acc[mi][nb*2],   ah[mi], bl);
                    mma_bf16(acc[mi][nb*2+1], ah[mi], bl + 2);
                }
                #pragma unroll
                for (int mi = 0; mi < 4; mi++) {
                    mma_bf16(acc[mi][nb*2],   al[mi], bh);
                    mma_bf16(acc[mi][nb*2+1], al[mi], bh + 2);
                }
            }
        }
        __syncthreads();
        if (c + 2 < nch) load_stage(s, c + 2);
    }

    // ---------------- epilogue ----------------
    const float m = (MODE == 0 || MODE == 2) ? mu[muidx] : 0.f;
    float* op = outf;
    if (MODE == 3) op = outf + (size_t)blockIdx.z * BATCH * MDIM;
    const int rbase = b0 + wr * 64 + (lane >> 2);
    const int cbase = p0 + wc * 32 + (lane & 3) * 2;

    #pragma unroll
    for (int mi = 0; mi < 4; mi++) {
        #pragma unroll
        for (int h = 0; h < 2; h++) {
            const int row = rbase + mi * 16 + h * 8;
            #pragma unroll
            for (int ni = 0; ni < 4; ni++) {
                const size_t off = (size_t)row * P + cbase + ni * 8;
                float v0 = acc[mi][ni][h * 2], v1 = acc[mi][ni][h * 2 + 1];
                if (MODE == 0) {
                    v0 *= m; v1 *= m;
                    split2(v0, v1, outh + off, outl + off);
                } else if (MODE == 2) {
                    __nv_bfloat162 h2 = *reinterpret_cast<const __nv_bfloat162*>(auxh + off);
                    __nv_bfloat162 l2 = *reinterpret_cast<const __nv_bfloat162*>(auxl + off);
                    float a0 = __bfloat162float(h2.x) + __bfloat162float(l2.x);
                    float a1 = __bfloat162float(h2.y) + __bfloat162float(l2.y);
                    v0 = a0 - m * v0; v1 = a1 - m * v1;
                    *reinterpret_cast<float2*>(op + off) = make_float2(v0, v1);
                } else {
                    *reinterpret_cast<float2*>(op + off) = make_float2(v0, v1);
                }
            }
        }
    }
}

// ---------------- shrink: exact kth-largest via bitwise binary search ----------------
// LAST=0: write splits only (xh/xl).  LAST=1: write x (final output) only.
template<int LAST>
__global__ __launch_bounds__(256, 4)
void shrink2(float* __restrict__ x, bf16* __restrict__ xh, bf16* __restrict__ xl,
             const float* __restrict__ beta, int bidx, int kth)
{
    __shared__ int wsum[2][8];
    const int tid = threadIdx.x, wid = tid >> 5, lane = tid & 31;
    float* row = x + (size_t)blockIdx.x * NDIM;
    const int e0 = tid * 8;

    float e[8];
    float4 a = *reinterpret_cast<const float4*>(row + e0);
    float4 b4 = *reinterpret_cast<const float4*>(row + e0 + 4);
    e[0]=a.x; e[1]=a.y; e[2]=a.z; e[3]=a.w; e[4]=b4.x; e[5]=b4.y; e[6]=b4.z; e[7]=b4.w;
    uint32_t k[8];
    #pragma unroll
    for (int i = 0; i < 8; i++) k[i] = __float_as_uint(fabsf(e[i]));

    uint32_t thr = 0;
    for (int bit = 30; bit >= 0; bit--) {
        uint32_t cand = thr | (1u << bit);
        int c = 0;
        #pragma unroll
        for (int i = 0; i < 8; i++) c += (k[i] >= cand);
        c = __reduce_add_sync(0xFFFFFFFFu, c);
        const int buf = bit & 1;
        if (lane == 0) wsum[buf][wid] = c;
        __syncthreads();
        int tot = wsum[buf][0]+wsum[buf][1]+wsum[buf][2]+wsum[buf][3]
                + wsum[buf][4]+wsum[buf][5]+wsum[buf][6]+wsum[buf][7];
        if (tot >= kth) thr = cand;
    }

    const float thf = __uint_as_float(thr);
    const float b = beta[bidx];
    float r[8];
    #pragma unroll
    for (int i = 0; i < 8; i++) {
        float val = e[i];
        float u = val / b;
        float soft = b * copysignf(fmaxf(fabsf(u) - 1.0f, 0.0f), u);
        r[i] = (fabsf(val) >= thf) ? val : soft;
    }

    if (LAST) {
        *reinterpret_cast<float4*>(row + e0)     = make_float4(r[0], r[1], r[2], r[3]);
        *reinterpret_cast<float4*>(row + e0 + 4) = make_float4(r[4], r[5], r[6], r[7]);
    } else {
        const size_t go = (size_t)blockIdx.x * NDIM + e0;
        #pragma unroll
        for (int i = 0; i < 8; i += 2)
            split2(r[i], r[i+1], xh + go + i, xl + go + i);
    }
}

// ---------------------------------------------------------------------------
extern "C" void kernel_launch(void* const* d_in, const int* in_sizes, int n_in,
                              void* d_out, int out_size)
{
    const float* y    = (const float*)d_in[0];   // [8192, 512]
    const float* A    = (const float*)d_in[1];   // [512, 2048]
    const float* W    = (const float*)d_in[2];   // [2048, 512] = A^T
    const float* beta = (const float*)d_in[3];
    const float* mu   = (const float*)d_in[4];
    float* x = (float*)d_out;                    // [8192, 2048]

    constexpr int SMEM_128 = 2 * (2 * 128 * PITCH + 2 * WT_B);   // 81920

    cudaFuncSetAttribute(mma_gemm<0>, cudaFuncAttributeMaxDynamicSharedMemorySize, SMEM_128);
    cudaFuncSetAttribute(mma_gemm<2>, cudaFuncAttributeMaxDynamicSharedMemorySize, SMEM_128);
    cudaFuncSetAttribute(mma_gemm<3>, cudaFuncAttributeMaxDynamicSharedMemorySize, SMEM_128);

    bf16 *xh, *xl, *rh, *rl, *yh, *yl, *Ahp, *Alp, *Wh, *Wl;
    float *part;
    { void* p; cudaGetSymbolAddress(&p, g_xh); xh = (bf16*)p; }
    { void* p; cudaGetSymbolAddress(&p, g_xl); xl = (bf16*)p; }
    { void* p; cudaGetSymbolAddress(&p, g_rh); rh = (bf16*)p; }
    { void* p; cudaGetSymbolAddress(&p, g_rl); rl = (bf16*)p; }
    { void* p; cudaGetSymbolAddress(&p, g_yh); yh = (bf16*)p; }
    { void* p; cudaGetSymbolAddress(&p, g_yl); yl = (bf16*)p; }
    { void* p; cudaGetSymbolAddress(&p, g_Ah); Ahp = (bf16*)p; }
    { void* p; cudaGetSymbolAddress(&p, g_Al); Alp = (bf16*)p; }
    { void* p; cudaGetSymbolAddress(&p, g_Wh); Wh = (bf16*)p; }
    { void* p; cudaGetSymbolAddress(&p, g_Wl); Wl = (bf16*)p; }
    { void* p; cudaGetSymbolAddress(&p, g_part); part = (float*)p; }

    // fused splits of all three inputs (one launch)
    {
        int total4 = NY4 + 2 * NA4;
        split3_kernel<<<(total4 + 255) / 256, 256>>>(y, yh, yl, A, Ahp, Alp, W, Wh, Wl);
    }

    const dim3 blk(256);
    const dim3 gN(BATCH / 128, NDIM / 128);       // (64, 16)  1024 CTAs
    const dim3 gM(BATCH / 128, MDIM / 128, 2);    // (64, 4, 2) 512 CTAs split-K
    const int kth[6] = {0, 24, 49, 73, 98, 122};
    const int nr4 = BATCH * MDIM / 4;

    // x0 = mu0 * (y @ A): splits only (x fp32 never consumed before GEMM2 rewrites it)
    mma_gemm<0><<<gN, blk, SMEM_128>>>(yh, yl, Wh, Wl, MDIM, NDIM,
                                       nullptr, xh, xl, nullptr, nullptr, mu, 0);

    for (int t = 1; t <= 5; t++) {
        // split-K partials of x @ A.T:  X = x splits (K=2048 halves), B = A rows, P=512
        mma_gemm<3><<<gM, blk, SMEM_128>>>(xh, xl, Ahp, Alp, NDIM, MDIM,
                                           part, nullptr, nullptr, nullptr, nullptr, mu, t);
        // r = p0 + p1 - y  -> rh/rl splits
        combine_r<<<(nr4 + 255) / 256, blk>>>(part, part + (size_t)BATCH * MDIM, y,
                                              rh, rl, nr4);
        // v = (xh+xl) - mu*(r @ W.T):  X = r splits (K=512), B = W rows, P=2048
        mma_gemm<2><<<gN, blk, SMEM_128>>>(rh, rl, Wh, Wl, MDIM, NDIM,
                                           x, nullptr, nullptr, xh, xl, mu, t);
        // x = shrink(v): t<5 -> splits only; t=5 -> final fp32 output
        if (t < 5)
            shrink2<0><<<BATCH, blk>>>(x, xh, xl, beta, t, kth[t]);
        else
            shrink2<1><<<BATCH, blk>>>(x, xh, xl, beta, t, kth[t]);
    }
}